// round 2
// baseline (speedup 1.0000x reference)
#include <cuda_runtime.h>
#include <math.h>

#define NN   100000
#define NE   1600000
#define INF  64
#define HIDD 128
#define NCLS 10

// ---------------- scratch (no allocations allowed) ----------------
__device__ int   g_is64;
__device__ float g_deg[NN];
__device__ float g_dinv[NN];
__device__ int   g_rows[NE];
__device__ int   g_cols[NE];
__device__ float g_norm[NE];
__device__ float4 g_agg1[NN * (INF / 4)];           // 25.6 MB : Â x   (float4 => 16B aligned)
__device__ float4 g_h1[(size_t)NN * (HIDD / 4)];    // 51.2 MB : relu(Â x W1 + b1)
__device__ float g_t2[NN * NCLS];                   // 4 MB    : h1 W2
__device__ float g_out2[NN * NCLS];                 // 4 MB    : Â t2 + b2
__device__ float g_acc[NCLS];

// ---------------- kernels ----------------

// Detect whether edge_index arrived as int64 or int32.
// int64 values < 100000 => every odd 32-bit word of the first 256 elements is 0.
__global__ void k_parse(const void* __restrict__ ei_raw) {
    __shared__ int s_nz;
    if (threadIdx.x == 0) s_nz = 0;
    __syncthreads();
    const unsigned int* w = (const unsigned int*)ei_raw;
    unsigned int v = w[threadIdx.x * 2 + 1];   // odd words of first 256 x 8 bytes
    if (v != 0u) atomicAdd(&s_nz, 1);
    __syncthreads();
    if (threadIdx.x == 0) g_is64 = (s_nz == 0) ? 1 : 0;
}

__global__ void k_init() {
    int i = blockIdx.x * blockDim.x + threadIdx.x;
    if (i < NN) g_deg[i] = 1.0f;      // self-loop contributes 1 to degree
    if (i < NCLS) g_acc[i] = 0.0f;
}

// Extract (row, col) per edge with dtype dispatch + defensive clamp.
__global__ void k_edges(const void* __restrict__ ei_raw) {
    int e = blockIdx.x * blockDim.x + threadIdx.x;
    if (e >= NE) return;
    int r, c;
    if (g_is64) {
        const long long* ei = (const long long*)ei_raw;
        r = (int)ei[e];
        c = (int)ei[NE + e];
    } else {
        const int* ei = (const int*)ei_raw;
        r = ei[e];
        c = ei[NE + e];
    }
    r = min(max(r, 0), NN - 1);
    c = min(max(c, 0), NN - 1);
    g_rows[e] = r;
    g_cols[e] = c;
}

__global__ void k_degree() {
    int e = blockIdx.x * blockDim.x + threadIdx.x;
    if (e < NE) atomicAdd(&g_deg[g_cols[e]], 1.0f);
}

__global__ void k_dinv() {
    int i = blockIdx.x * blockDim.x + threadIdx.x;
    if (i < NN) g_dinv[i] = rsqrtf(g_deg[i]);
}

__global__ void k_norm() {
    int e = blockIdx.x * blockDim.x + threadIdx.x;
    if (e < NE) g_norm[e] = g_dinv[g_rows[e]] * g_dinv[g_cols[e]];
}

// self-loop message for layer 1: agg1[i] = dinv[i]^2 * x[i]
__global__ void k_self1(const float* __restrict__ x) {
    int idx = blockIdx.x * blockDim.x + threadIdx.x;   // NN*16 float4 items
    if (idx < NN * 16) {
        int node = idx >> 4;
        float d = g_dinv[node];
        float s = d * d;
        float4 v = ((const float4*)x)[idx];
        v.x *= s; v.y *= s; v.z *= s; v.w *= s;
        g_agg1[idx] = v;
    }
}

// layer-1 aggregation over edges: agg1[col] += norm * x[row]  (64 feats, 16 thr/edge)
__global__ void k_scatter1(const float* __restrict__ x) {
    int idx = blockIdx.x * blockDim.x + threadIdx.x;   // NE*16
    if (idx >= NE * 16) return;
    int e = idx >> 4, q = idx & 15;
    float n = g_norm[e];
    int r = g_rows[e], c = g_cols[e];
    float4 v = ((const float4*)x)[r * 16 + q];
    float* dst = (float*)&g_agg1[c * 16 + q];
    atomicAdd(dst + 0, v.x * n);
    atomicAdd(dst + 1, v.y * n);
    atomicAdd(dst + 2, v.z * n);
    atomicAdd(dst + 3, v.w * n);
}

// h1 = relu(agg1 @ W1 + b1), tile 64 nodes x 128 cols, 256 threads (8x4 micro)
__global__ void k_gemm1(const float* __restrict__ W1, const float* __restrict__ b1) {
    __shared__ float As[64 * 64];    // 16 KB
    __shared__ float Bs[64 * 128];   // 32 KB
    int tid = threadIdx.x;
    int bnode = blockIdx.x * 64;

    for (int t = tid; t < (64 * 128) / 4; t += 256)
        ((float4*)Bs)[t] = ((const float4*)W1)[t];
    for (int t = tid; t < 64 * 16; t += 256) {
        int lr = t >> 4, q = t & 15;
        int node = bnode + lr;
        float4 v = (node < NN) ? g_agg1[node * 16 + q]
                               : make_float4(0.f, 0.f, 0.f, 0.f);
        ((float4*)As)[t] = v;
    }
    __syncthreads();

    int tx = tid & 31, ty = tid >> 5;     // cols = tx*4..+3, rows = ty*8..+7
    float acc[8][4];
    #pragma unroll
    for (int i = 0; i < 8; i++)
        #pragma unroll
        for (int j = 0; j < 4; j++) acc[i][j] = 0.0f;

    #pragma unroll 4
    for (int k = 0; k < 64; k++) {
        float4 bb = ((const float4*)Bs)[k * 32 + tx];
        #pragma unroll
        for (int i = 0; i < 8; i++) {
            float a = As[(ty * 8 + i) * 64 + k];
            acc[i][0] = fmaf(a, bb.x, acc[i][0]);
            acc[i][1] = fmaf(a, bb.y, acc[i][1]);
            acc[i][2] = fmaf(a, bb.z, acc[i][2]);
            acc[i][3] = fmaf(a, bb.w, acc[i][3]);
        }
    }

    float4 bias = ((const float4*)b1)[tx];
    #pragma unroll
    for (int i = 0; i < 8; i++) {
        int node = bnode + ty * 8 + i;
        if (node < NN) {
            float4 o;
            o.x = fmaxf(acc[i][0] + bias.x, 0.0f);
            o.y = fmaxf(acc[i][1] + bias.y, 0.0f);
            o.z = fmaxf(acc[i][2] + bias.z, 0.0f);
            o.w = fmaxf(acc[i][3] + bias.w, 0.0f);
            g_h1[(size_t)node * 32 + tx] = o;
        }
    }
}

// t2 = h1 @ W2   (thread per node, W2 in smem)
__global__ void k_gemm2(const float* __restrict__ W2) {
    __shared__ float Ws[HIDD * NCLS];
    int tid = threadIdx.x;
    for (int t = tid; t < HIDD * NCLS; t += blockDim.x) Ws[t] = W2[t];
    __syncthreads();
    int node = blockIdx.x * blockDim.x + tid;
    if (node >= NN) return;
    float acc[NCLS];
    #pragma unroll
    for (int c = 0; c < NCLS; c++) acc[c] = 0.0f;
    const float4* row = &g_h1[(size_t)node * 32];
    #pragma unroll 8
    for (int kk = 0; kk < 32; kk++) {
        float4 h = row[kk];
        const float* w = &Ws[kk * 4 * NCLS];
        #pragma unroll
        for (int c = 0; c < NCLS; c++)
            acc[c] += h.x * w[c] + h.y * w[NCLS + c] + h.z * w[2 * NCLS + c] + h.w * w[3 * NCLS + c];
    }
    #pragma unroll
    for (int c = 0; c < NCLS; c++) g_t2[node * NCLS + c] = acc[c];
}

// out2 = self-loop msg + bias
__global__ void k_self2(const float* __restrict__ b2) {
    int idx = blockIdx.x * blockDim.x + threadIdx.x;   // NN*NCLS
    if (idx < NN * NCLS) {
        int node = idx / NCLS;
        int c = idx - node * NCLS;
        float d = g_dinv[node];
        g_out2[idx] = d * d * g_t2[idx] + b2[c];
    }
}

// layer-2 aggregation: out2[col][c] += norm * t2[row][c]
__global__ void k_scatter2() {
    int idx = blockIdx.x * blockDim.x + threadIdx.x;   // NE*NCLS = 16M
    if (idx >= NE * NCLS) return;
    int e = idx / NCLS;
    int c = idx - e * NCLS;
    float v = g_norm[e] * g_t2[g_rows[e] * NCLS + c];
    atomicAdd(&g_out2[g_cols[e] * NCLS + c], v);
}

// per-node log_softmax, block-reduce per class, atomic into g_acc
__global__ void k_final() {
    __shared__ float sred[NCLS * 256];
    int tid = threadIdx.x;
    int node = blockIdx.x * 256 + tid;
    float loc[NCLS];
    #pragma unroll
    for (int c = 0; c < NCLS; c++) loc[c] = 0.0f;
    if (node < NN) {
        float v[NCLS];
        float m = -1e30f;
        #pragma unroll
        for (int c = 0; c < NCLS; c++) {
            v[c] = g_out2[node * NCLS + c];
            m = fmaxf(m, v[c]);
        }
        float s = 0.0f;
        #pragma unroll
        for (int c = 0; c < NCLS; c++) s += expf(v[c] - m);
        float lse = m + logf(s);
        #pragma unroll
        for (int c = 0; c < NCLS; c++) loc[c] = v[c] - lse;
    }
    #pragma unroll
    for (int c = 0; c < NCLS; c++) sred[c * 256 + tid] = loc[c];
    __syncthreads();
    for (int st = 128; st > 0; st >>= 1) {
        if (tid < st) {
            #pragma unroll
            for (int c = 0; c < NCLS; c++)
                sred[c * 256 + tid] += sred[c * 256 + tid + st];
        }
        __syncthreads();
    }
    if (tid < NCLS) atomicAdd(&g_acc[tid], sred[tid * 256]);
}

__global__ void k_out(float* __restrict__ out) {
    int c = threadIdx.x;
    if (c < NCLS) out[c] = g_acc[c] * (1.0f / (float)NN);
}

// ---------------- launch ----------------
extern "C" void kernel_launch(void* const* d_in, const int* in_sizes, int n_in,
                              void* d_out, int out_size) {
    const float* x  = (const float*)d_in[0];
    const void*  ei = d_in[1];
    const float* W1 = (const float*)d_in[2];
    const float* b1 = (const float*)d_in[3];
    const float* W2 = (const float*)d_in[4];
    const float* b2 = (const float*)d_in[5];
    float* out = (float*)d_out;

    k_parse   <<<1, 256>>>(ei);
    k_init    <<<(NN + 255) / 256, 256>>>();
    k_edges   <<<(NE + 255) / 256, 256>>>(ei);
    k_degree  <<<(NE + 255) / 256, 256>>>();
    k_dinv    <<<(NN + 255) / 256, 256>>>();
    k_norm    <<<(NE + 255) / 256, 256>>>();
    k_self1   <<<(NN * 16 + 255) / 256, 256>>>(x);
    k_scatter1<<<(NE * 16 + 255) / 256, 256>>>(x);
    k_gemm1   <<<(NN + 63) / 64, 256>>>(W1, b1);
    k_gemm2   <<<(NN + 255) / 256, 256>>>(W2);
    k_self2   <<<(NN * NCLS + 255) / 256, 256>>>(b2);
    k_scatter2<<<(NE * NCLS + 255) / 256, 256>>>();
    k_final   <<<(NN + 255) / 256, 256>>>();
    k_out     <<<1, 32>>>(out);
}

// round 3
// speedup vs baseline: 1.6562x; 1.6562x over previous
#include <cuda_runtime.h>
#include <math.h>

#define NN   100000
#define NE   1600000
#define INF  64
#define HIDD 128
#define NCLS 10

// ---------------- scratch (no allocations allowed) ----------------
__device__ int   g_is64;
__device__ float g_deg[NN];
__device__ float g_dinv[NN];
__device__ int   g_rows[NE];
__device__ int   g_cols[NE];
__device__ float g_norm[NE];
__device__ float4 g_agg1[NN * (INF / 4)];           // 25.6 MB : Â x
__device__ float4 g_h1[(size_t)NN * (HIDD / 4)];    // 51.2 MB : relu(Â x W1 + b1)
__device__ float g_t2[NN * NCLS];                   // 4 MB    : h1 W2
__device__ float g_out2[NN * NCLS];                 // 4 MB    : Â t2 + b2
__device__ float g_acc[NCLS];

// ---------------- kernels ----------------

// Detect whether edge_index arrived as int64 or int32.
__global__ void k_parse(const void* __restrict__ ei_raw) {
    __shared__ int s_nz;
    if (threadIdx.x == 0) s_nz = 0;
    __syncthreads();
    const unsigned int* w = (const unsigned int*)ei_raw;
    unsigned int v = w[threadIdx.x * 2 + 1];
    if (v != 0u) atomicAdd(&s_nz, 1);
    __syncthreads();
    if (threadIdx.x == 0) g_is64 = (s_nz == 0) ? 1 : 0;
}

__global__ void k_init() {
    int i = blockIdx.x * blockDim.x + threadIdx.x;
    if (i < NN) g_deg[i] = 1.0f;      // self-loop contributes 1
    if (i < NCLS) g_acc[i] = 0.0f;
}

// Extract (row, col), clamp, and accumulate degree — fused single pass.
__global__ void k_edges_degree(const void* __restrict__ ei_raw) {
    int e = blockIdx.x * blockDim.x + threadIdx.x;
    if (e >= NE) return;
    int r, c;
    if (g_is64) {
        const long long* ei = (const long long*)ei_raw;
        r = (int)ei[e];
        c = (int)ei[NE + e];
    } else {
        const int* ei = (const int*)ei_raw;
        r = ei[e];
        c = ei[NE + e];
    }
    r = min(max(r, 0), NN - 1);
    c = min(max(c, 0), NN - 1);
    g_rows[e] = r;
    g_cols[e] = c;
    atomicAdd(&g_deg[c], 1.0f);
}

__global__ void k_dinv() {
    int i = blockIdx.x * blockDim.x + threadIdx.x;
    if (i < NN) g_dinv[i] = rsqrtf(g_deg[i]);
}

__global__ void k_norm() {
    int e = blockIdx.x * blockDim.x + threadIdx.x;
    if (e < NE) g_norm[e] = g_dinv[g_rows[e]] * g_dinv[g_cols[e]];
}

// self-loop message for layer 1: agg1[i] = dinv[i]^2 * x[i]
__global__ void k_self1(const float* __restrict__ x) {
    int idx = blockIdx.x * blockDim.x + threadIdx.x;   // NN*16 float4 items
    if (idx < NN * 16) {
        int node = idx >> 4;
        float d = g_dinv[node];
        float s = d * d;
        float4 v = ((const float4*)x)[idx];
        v.x *= s; v.y *= s; v.z *= s; v.w *= s;
        g_agg1[idx] = v;
    }
}

// layer-1 aggregation: agg1[col] += norm * x[row], 16 thr/edge, ONE v4 atomic each
__global__ void k_scatter1(const float* __restrict__ x) {
    int idx = blockIdx.x * blockDim.x + threadIdx.x;   // NE*16
    if (idx >= NE * 16) return;
    int e = idx >> 4, q = idx & 15;
    float n = g_norm[e];
    int r = g_rows[e], c = g_cols[e];
    float4 v = ((const float4*)x)[r * 16 + q];
    v.x *= n; v.y *= n; v.z *= n; v.w *= n;
    atomicAdd(&g_agg1[c * 16 + q], v);                 // RED.E.ADD.F32.V4
}

// h1 = relu(agg1 @ W1 + b1), tile 64 nodes x 128 cols, 256 threads (8x4 micro)
__global__ void k_gemm1(const float* __restrict__ W1, const float* __restrict__ b1) {
    __shared__ float As[64 * 64];
    __shared__ float Bs[64 * 128];
    int tid = threadIdx.x;
    int bnode = blockIdx.x * 64;

    for (int t = tid; t < (64 * 128) / 4; t += 256)
        ((float4*)Bs)[t] = ((const float4*)W1)[t];
    for (int t = tid; t < 64 * 16; t += 256) {
        int lr = t >> 4, q = t & 15;
        int node = bnode + lr;
        float4 v = (node < NN) ? g_agg1[node * 16 + q]
                               : make_float4(0.f, 0.f, 0.f, 0.f);
        ((float4*)As)[t] = v;
    }
    __syncthreads();

    int tx = tid & 31, ty = tid >> 5;
    float acc[8][4];
    #pragma unroll
    for (int i = 0; i < 8; i++)
        #pragma unroll
        for (int j = 0; j < 4; j++) acc[i][j] = 0.0f;

    #pragma unroll 4
    for (int k = 0; k < 64; k++) {
        float4 bb = ((const float4*)Bs)[k * 32 + tx];
        #pragma unroll
        for (int i = 0; i < 8; i++) {
            float a = As[(ty * 8 + i) * 64 + k];
            acc[i][0] = fmaf(a, bb.x, acc[i][0]);
            acc[i][1] = fmaf(a, bb.y, acc[i][1]);
            acc[i][2] = fmaf(a, bb.z, acc[i][2]);
            acc[i][3] = fmaf(a, bb.w, acc[i][3]);
        }
    }

    float4 bias = ((const float4*)b1)[tx];
    #pragma unroll
    for (int i = 0; i < 8; i++) {
        int node = bnode + ty * 8 + i;
        if (node < NN) {
            float4 o;
            o.x = fmaxf(acc[i][0] + bias.x, 0.0f);
            o.y = fmaxf(acc[i][1] + bias.y, 0.0f);
            o.z = fmaxf(acc[i][2] + bias.z, 0.0f);
            o.w = fmaxf(acc[i][3] + bias.w, 0.0f);
            g_h1[(size_t)node * 32 + tx] = o;
        }
    }
}

// t2 = h1 @ W2   (thread per node, W2 in smem)
__global__ void k_gemm2(const float* __restrict__ W2) {
    __shared__ float Ws[HIDD * NCLS];
    int tid = threadIdx.x;
    for (int t = tid; t < HIDD * NCLS; t += blockDim.x) Ws[t] = W2[t];
    __syncthreads();
    int node = blockIdx.x * blockDim.x + tid;
    if (node >= NN) return;
    float acc[NCLS];
    #pragma unroll
    for (int c = 0; c < NCLS; c++) acc[c] = 0.0f;
    const float4* row = &g_h1[(size_t)node * 32];
    #pragma unroll 8
    for (int kk = 0; kk < 32; kk++) {
        float4 h = row[kk];
        const float* w = &Ws[kk * 4 * NCLS];
        #pragma unroll
        for (int c = 0; c < NCLS; c++)
            acc[c] += h.x * w[c] + h.y * w[NCLS + c] + h.z * w[2 * NCLS + c] + h.w * w[3 * NCLS + c];
    }
    #pragma unroll
    for (int c = 0; c < NCLS; c++) g_t2[node * NCLS + c] = acc[c];
}

// out2 = self-loop msg + bias
__global__ void k_self2(const float* __restrict__ b2) {
    int idx = blockIdx.x * blockDim.x + threadIdx.x;   // NN*NCLS
    if (idx < NN * NCLS) {
        int node = idx / NCLS;
        int c = idx - node * NCLS;
        float d = g_dinv[node];
        g_out2[idx] = d * d * g_t2[idx] + b2[c];
    }
}

// layer-2 aggregation: 5 thr/edge, float2 atomics (8B aligned since NCLS*4=40, 2q*4 even)
__global__ void k_scatter2() {
    int idx = blockIdx.x * blockDim.x + threadIdx.x;   // NE*5 = 8M
    if (idx >= NE * 5) return;
    int e = idx / 5;
    int q = idx - e * 5;                                // class pair
    float n = g_norm[e];
    int r = g_rows[e], c = g_cols[e];
    float2 v = *(const float2*)&g_t2[r * NCLS + 2 * q];
    v.x *= n; v.y *= n;
    atomicAdd((float2*)&g_out2[c * NCLS + 2 * q], v);  // RED.E.ADD.F32.V2
}

// per-node log_softmax, block-reduce per class, atomic into g_acc
__global__ void k_final() {
    __shared__ float sred[NCLS * 256];
    int tid = threadIdx.x;
    int node = blockIdx.x * 256 + tid;
    float loc[NCLS];
    #pragma unroll
    for (int c = 0; c < NCLS; c++) loc[c] = 0.0f;
    if (node < NN) {
        float v[NCLS];
        float m = -1e30f;
        #pragma unroll
        for (int c = 0; c < NCLS; c++) {
            v[c] = g_out2[node * NCLS + c];
            m = fmaxf(m, v[c]);
        }
        float s = 0.0f;
        #pragma unroll
        for (int c = 0; c < NCLS; c++) s += expf(v[c] - m);
        float lse = m + logf(s);
        #pragma unroll
        for (int c = 0; c < NCLS; c++) loc[c] = v[c] - lse;
    }
    #pragma unroll
    for (int c = 0; c < NCLS; c++) sred[c * 256 + tid] = loc[c];
    __syncthreads();
    for (int st = 128; st > 0; st >>= 1) {
        if (tid < st) {
            #pragma unroll
            for (int c = 0; c < NCLS; c++)
                sred[c * 256 + tid] += sred[c * 256 + tid + st];
        }
        __syncthreads();
    }
    if (tid < NCLS) atomicAdd(&g_acc[tid], sred[tid * 256]);
}

__global__ void k_out(float* __restrict__ out) {
    int c = threadIdx.x;
    if (c < NCLS) out[c] = g_acc[c] * (1.0f / (float)NN);
}

// ---------------- launch ----------------
extern "C" void kernel_launch(void* const* d_in, const int* in_sizes, int n_in,
                              void* d_out, int out_size) {
    const float* x  = (const float*)d_in[0];
    const void*  ei = d_in[1];
    const float* W1 = (const float*)d_in[2];
    const float* b1 = (const float*)d_in[3];
    const float* W2 = (const float*)d_in[4];
    const float* b2 = (const float*)d_in[5];
    float* out = (float*)d_out;

    k_parse       <<<1, 256>>>(ei);
    k_init        <<<(NN + 255) / 256, 256>>>();
    k_edges_degree<<<(NE + 255) / 256, 256>>>(ei);
    k_dinv        <<<(NN + 255) / 256, 256>>>();
    k_norm        <<<(NE + 255) / 256, 256>>>();
    k_self1       <<<(NN * 16 + 255) / 256, 256>>>(x);
    k_scatter1    <<<(NE * 16 + 255) / 256, 256>>>(x);
    k_gemm1       <<<(NN + 63) / 64, 256>>>(W1, b1);
    k_gemm2       <<<(NN + 255) / 256, 256>>>(W2);
    k_self2       <<<(NN * NCLS + 255) / 256, 256>>>(b2);
    k_scatter2    <<<(NE * 5 + 255) / 256, 256>>>();
    k_final       <<<(NN + 255) / 256, 256>>>();
    k_out         <<<1, 32>>>(out);
}

// round 4
// speedup vs baseline: 1.6896x; 1.0202x over previous
#include <cuda_runtime.h>
#include <math.h>

#define NN   100000
#define NE   1600000
#define INF  64
#define HIDD 128
#define NCLS 10
#define NCP  12          // padded class dim (48B/node, float4-friendly)

// ---------------- scratch (no allocations allowed) ----------------
__device__ int   g_is64;
__device__ float g_deg[NN];
__device__ float g_dinv[NN];
__device__ int   g_rows[NE];
__device__ int   g_cols[NE];
__device__ float g_norm[NE];                         // written by scatter1 leaders, read by scatter2
__device__ float4 g_agg1[NN * (INF / 4)];            // 25.6 MB : Â x
__device__ float4 g_h1[(size_t)NN * (HIDD / 4)];     // 51.2 MB : relu(Â x W1 + b1)
__device__ float g_t2p[NN * NCP];                    // 4.8 MB  : h1 W2 (padded)
__device__ float g_out2p[NN * NCP];                  // 4.8 MB  : Â t2 + b2 (padded)
__device__ float g_acc[NCLS];

// ---------------- kernels ----------------

// Detect whether edge_index arrived as int64 or int32.
__global__ void k_parse(const void* __restrict__ ei_raw) {
    __shared__ int s_nz;
    if (threadIdx.x == 0) s_nz = 0;
    __syncthreads();
    const unsigned int* w = (const unsigned int*)ei_raw;
    unsigned int v = w[threadIdx.x * 2 + 1];
    if (v != 0u) atomicAdd(&s_nz, 1);
    __syncthreads();
    if (threadIdx.x == 0) g_is64 = (s_nz == 0) ? 1 : 0;
}

__global__ void k_init() {
    int i = blockIdx.x * blockDim.x + threadIdx.x;
    if (i < NN) g_deg[i] = 1.0f;      // self-loop contributes 1
    if (i < NCLS) g_acc[i] = 0.0f;
}

// Extract (row, col), clamp, accumulate degree — fused single pass.
__global__ void k_edges_degree(const void* __restrict__ ei_raw) {
    int e = blockIdx.x * blockDim.x + threadIdx.x;
    if (e >= NE) return;
    int r, c;
    if (g_is64) {
        const long long* ei = (const long long*)ei_raw;
        r = (int)ei[e];
        c = (int)ei[NE + e];
    } else {
        const int* ei = (const int*)ei_raw;
        r = ei[e];
        c = ei[NE + e];
    }
    r = min(max(r, 0), NN - 1);
    c = min(max(c, 0), NN - 1);
    g_rows[e] = r;
    g_cols[e] = c;
    atomicAdd(&g_deg[c], 1.0f);
}

__global__ void k_dinv() {
    int i = blockIdx.x * blockDim.x + threadIdx.x;
    if (i < NN) g_dinv[i] = rsqrtf(g_deg[i]);
}

// self-loop message for layer 1: agg1[i] = dinv[i]^2 * x[i]
__global__ void k_self1(const float* __restrict__ x) {
    int idx = blockIdx.x * blockDim.x + threadIdx.x;   // NN*16 float4 items
    if (idx < NN * 16) {
        int node = idx >> 4;
        float d = g_dinv[node];
        float s = d * d;
        float4 v = ((const float4*)x)[idx];
        v.x *= s; v.y *= s; v.z *= s; v.w *= s;
        g_agg1[idx] = v;
    }
}

// layer-1 aggregation: warp = 2 edges (16 lanes each). Leader lanes (q==0) load
// r,c, compute norm (and persist it for scatter2); shfl-broadcast to the group.
// One v4 REDG per lane. Grid is exact: NE*16 threads.
__global__ void k_scatter1(const float* __restrict__ x) {
    int idx  = blockIdx.x * blockDim.x + threadIdx.x;  // < NE*16 exactly
    int lane = idx & 31;
    int q    = lane & 15;
    int e    = (idx >> 5) * 2 + (lane >> 4);
    int r = 0, c = 0;
    float n = 0.0f;
    if (q == 0) {
        r = g_rows[e];
        c = g_cols[e];
        n = g_dinv[r] * g_dinv[c];
        g_norm[e] = n;
    }
    int src = lane & 16;
    r = __shfl_sync(0xffffffffu, r, src);
    c = __shfl_sync(0xffffffffu, c, src);
    n = __shfl_sync(0xffffffffu, n, src);
    float4 v = ((const float4*)x)[r * 16 + q];
    v.x *= n; v.y *= n; v.z *= n; v.w *= n;
    atomicAdd(&g_agg1[c * 16 + q], v);                 // RED.E.ADD.F32.V4
}

// h1 = relu(agg1 @ W1 + b1), tile 64 nodes x 128 cols, 256 threads (8x4 micro)
__global__ void k_gemm1(const float* __restrict__ W1, const float* __restrict__ b1) {
    __shared__ float As[64 * 64];
    __shared__ float Bs[64 * 128];
    int tid = threadIdx.x;
    int bnode = blockIdx.x * 64;

    for (int t = tid; t < (64 * 128) / 4; t += 256)
        ((float4*)Bs)[t] = ((const float4*)W1)[t];
    for (int t = tid; t < 64 * 16; t += 256) {
        int lr = t >> 4, q = t & 15;
        int node = bnode + lr;
        float4 v = (node < NN) ? g_agg1[node * 16 + q]
                               : make_float4(0.f, 0.f, 0.f, 0.f);
        ((float4*)As)[t] = v;
    }
    __syncthreads();

    int tx = tid & 31, ty = tid >> 5;
    float acc[8][4];
    #pragma unroll
    for (int i = 0; i < 8; i++)
        #pragma unroll
        for (int j = 0; j < 4; j++) acc[i][j] = 0.0f;

    #pragma unroll 4
    for (int k = 0; k < 64; k++) {
        float4 bb = ((const float4*)Bs)[k * 32 + tx];
        #pragma unroll
        for (int i = 0; i < 8; i++) {
            float a = As[(ty * 8 + i) * 64 + k];
            acc[i][0] = fmaf(a, bb.x, acc[i][0]);
            acc[i][1] = fmaf(a, bb.y, acc[i][1]);
            acc[i][2] = fmaf(a, bb.z, acc[i][2]);
            acc[i][3] = fmaf(a, bb.w, acc[i][3]);
        }
    }

    float4 bias = ((const float4*)b1)[tx];
    #pragma unroll
    for (int i = 0; i < 8; i++) {
        int node = bnode + ty * 8 + i;
        if (node < NN) {
            float4 o;
            o.x = fmaxf(acc[i][0] + bias.x, 0.0f);
            o.y = fmaxf(acc[i][1] + bias.y, 0.0f);
            o.z = fmaxf(acc[i][2] + bias.z, 0.0f);
            o.w = fmaxf(acc[i][3] + bias.w, 0.0f);
            g_h1[(size_t)node * 32 + tx] = o;
        }
    }
}

// t2p = h1 @ W2 (padded to 12 cols, last two zero)
__global__ void k_gemm2(const float* __restrict__ W2) {
    __shared__ float Ws[HIDD * NCLS];
    int tid = threadIdx.x;
    for (int t = tid; t < HIDD * NCLS; t += blockDim.x) Ws[t] = W2[t];
    __syncthreads();
    int node = blockIdx.x * blockDim.x + tid;
    if (node >= NN) return;
    float acc[NCLS];
    #pragma unroll
    for (int c = 0; c < NCLS; c++) acc[c] = 0.0f;
    const float4* row = &g_h1[(size_t)node * 32];
    #pragma unroll 8
    for (int kk = 0; kk < 32; kk++) {
        float4 h = row[kk];
        const float* w = &Ws[kk * 4 * NCLS];
        #pragma unroll
        for (int c = 0; c < NCLS; c++)
            acc[c] += h.x * w[c] + h.y * w[NCLS + c] + h.z * w[2 * NCLS + c] + h.w * w[3 * NCLS + c];
    }
    #pragma unroll
    for (int c = 0; c < NCLS; c++) g_t2p[node * NCP + c] = acc[c];
    g_t2p[node * NCP + 10] = 0.0f;
    g_t2p[node * NCP + 11] = 0.0f;
}

// out2p = self-loop msg + bias (pad cols -> 0)
__global__ void k_self2(const float* __restrict__ b2) {
    int idx = blockIdx.x * blockDim.x + threadIdx.x;   // NN*NCP
    if (idx < NN * NCP) {
        int node = idx / NCP;
        int c = idx - node * NCP;
        float d = g_dinv[node];
        g_out2p[idx] = (c < NCLS) ? d * d * g_t2p[idx] + b2[c] : 0.0f;
    }
}

// layer-2 aggregation: 3 thr/edge, v4 atomics on padded rows (48B/node)
__global__ void k_scatter2() {
    int idx = blockIdx.x * blockDim.x + threadIdx.x;   // < NE*3 exactly
    int e = idx / 3;
    int q = idx - e * 3;
    float n = g_norm[e];
    int r = g_rows[e], c = g_cols[e];
    float4 v = *(const float4*)&g_t2p[r * NCP + 4 * q];
    v.x *= n; v.y *= n; v.z *= n; v.w *= n;
    atomicAdd((float4*)&g_out2p[c * NCP + 4 * q], v);  // RED.E.ADD.F32.V4
}

// per-node log_softmax, block-reduce per class, atomic into g_acc
__global__ void k_final() {
    __shared__ float sred[NCLS * 256];
    int tid = threadIdx.x;
    int node = blockIdx.x * 256 + tid;
    float loc[NCLS];
    #pragma unroll
    for (int c = 0; c < NCLS; c++) loc[c] = 0.0f;
    if (node < NN) {
        const float4* rowp = (const float4*)&g_out2p[node * NCP];
        float4 a = rowp[0], b = rowp[1], d4 = rowp[2];
        float v[NCLS] = {a.x, a.y, a.z, a.w, b.x, b.y, b.z, b.w, d4.x, d4.y};
        float m = -1e30f;
        #pragma unroll
        for (int c = 0; c < NCLS; c++) m = fmaxf(m, v[c]);
        float s = 0.0f;
        #pragma unroll
        for (int c = 0; c < NCLS; c++) s += expf(v[c] - m);
        float lse = m + logf(s);
        #pragma unroll
        for (int c = 0; c < NCLS; c++) loc[c] = v[c] - lse;
    }
    #pragma unroll
    for (int c = 0; c < NCLS; c++) sred[c * 256 + tid] = loc[c];
    __syncthreads();
    for (int st = 128; st > 0; st >>= 1) {
        if (tid < st) {
            #pragma unroll
            for (int c = 0; c < NCLS; c++)
                sred[c * 256 + tid] += sred[c * 256 + tid + st];
        }
        __syncthreads();
    }
    if (tid < NCLS) atomicAdd(&g_acc[tid], sred[tid * 256]);
}

__global__ void k_out(float* __restrict__ out) {
    int c = threadIdx.x;
    if (c < NCLS) out[c] = g_acc[c] * (1.0f / (float)NN);
}

// ---------------- launch ----------------
extern "C" void kernel_launch(void* const* d_in, const int* in_sizes, int n_in,
                              void* d_out, int out_size) {
    const float* x  = (const float*)d_in[0];
    const void*  ei = d_in[1];
    const float* W1 = (const float*)d_in[2];
    const float* b1 = (const float*)d_in[3];
    const float* W2 = (const float*)d_in[4];
    const float* b2 = (const float*)d_in[5];
    float* out = (float*)d_out;

    k_parse       <<<1, 256>>>(ei);
    k_init        <<<(NN + 255) / 256, 256>>>();
    k_edges_degree<<<(NE + 255) / 256, 256>>>(ei);
    k_dinv        <<<(NN + 255) / 256, 256>>>();
    k_self1       <<<(NN * 16 + 255) / 256, 256>>>(x);
    k_scatter1    <<<(NE * 16) / 256, 256>>>(x);          // exact
    k_gemm1       <<<(NN + 63) / 64, 256>>>(W1, b1);
    k_gemm2       <<<(NN + 255) / 256, 256>>>(W2);
    k_self2       <<<(NN * NCP + 255) / 256, 256>>>(b2);
    k_scatter2    <<<(NE * 3) / 256, 256>>>();            // exact
    k_final       <<<(NN + 255) / 256, 256>>>();
    k_out         <<<1, 32>>>(out);
}

// round 5
// speedup vs baseline: 1.8416x; 1.0900x over previous
#include <cuda_runtime.h>
#include <cuda_fp16.h>
#include <math.h>

#define NN   100000
#define NE   1600000
#define INF  64
#define HIDD 128
#define NCLS 10
#define NCP  12
#define NB   ((NN + 255) / 256)     // 391 scan blocks

// ---------------- scratch (no allocations allowed) ----------------
__device__ int   g_is64;
__device__ int   g_cnt[NN];          // in-degree (excl self)
__device__ int   g_cur[NN];          // fill cursors
__device__ int   g_offs[NN + 1];     // CSR offsets
__device__ int   g_bsum[NB];
__device__ int   g_bpre[NB];
__device__ float g_dinv[NN];
__device__ int   g_rows[NE];
__device__ int   g_cols[NE];
__device__ int2  g_meta[NE];         // {src, norm-as-int} per CSR slot
__device__ __half2 g_xh[NN * 32];    // 12.8 MB : x in half
__device__ float4 g_agg1[NN * (INF / 4)];          // 25.6 MB : Â x
__device__ float4 g_h1[(size_t)NN * (HIDD / 4)];   // 51.2 MB
__device__ float g_t2p[NN * NCP];                  // 4.8 MB (pads unwritten/unused)
__device__ float g_out2p[NN * NCP];                // 4.8 MB
__device__ float g_acc[NCLS];

// ---------------- kernels ----------------

__global__ void k_parse(const void* __restrict__ ei_raw) {
    __shared__ int s_nz;
    if (threadIdx.x == 0) s_nz = 0;
    __syncthreads();
    const unsigned int* w = (const unsigned int*)ei_raw;
    if (w[threadIdx.x * 2 + 1] != 0u) atomicAdd(&s_nz, 1);
    __syncthreads();
    if (threadIdx.x == 0) g_is64 = (s_nz == 0) ? 1 : 0;
}

__global__ void k_init() {
    int i = blockIdx.x * blockDim.x + threadIdx.x;
    if (i < NN) { g_cnt[i] = 0; g_cur[i] = 0; }
    if (i < NCLS) g_acc[i] = 0.0f;
}

// decode edges (dtype dispatch + clamp) and histogram destinations
__global__ void k_edges_degree(const void* __restrict__ ei_raw) {
    int e = blockIdx.x * blockDim.x + threadIdx.x;
    if (e >= NE) return;
    int r, c;
    if (g_is64) {
        const long long* ei = (const long long*)ei_raw;
        r = (int)ei[e];  c = (int)ei[NE + e];
    } else {
        const int* ei = (const int*)ei_raw;
        r = ei[e];       c = ei[NE + e];
    }
    r = min(max(r, 0), NN - 1);
    c = min(max(c, 0), NN - 1);
    g_rows[e] = r;
    g_cols[e] = c;
    atomicAdd(&g_cnt[c], 1);
}

__global__ void k_dinv() {
    int i = blockIdx.x * blockDim.x + threadIdx.x;
    if (i < NN) g_dinv[i] = rsqrtf((float)(g_cnt[i] + 1));   // +1 self-loop
}

// x -> half2 (packed pairs)
__global__ void k_xhalf(const float* __restrict__ x) {
    int i = blockIdx.x * blockDim.x + threadIdx.x;   // NN*32
    if (i < NN * 32) {
        float2 v = ((const float2*)x)[i];
        g_xh[i] = __floats2half2_rn(v.x, v.y);
    }
}

// ---- 3-kernel exclusive scan of g_cnt -> g_offs ----
__global__ void k_scanA() {
    __shared__ int s[256];
    int tid = threadIdx.x;
    int i = blockIdx.x * 256 + tid;
    int v = (i < NN) ? g_cnt[i] : 0;
    s[tid] = v;
    __syncthreads();
    #pragma unroll
    for (int st = 1; st < 256; st <<= 1) {
        int t = (tid >= st) ? s[tid - st] : 0;
        __syncthreads();
        s[tid] += t;
        __syncthreads();
    }
    if (i < NN) g_offs[i] = s[tid] - v;
    if (tid == 255) g_bsum[blockIdx.x] = s[255];
}

__global__ void k_scanB() {
    __shared__ int s[512];
    int tid = threadIdx.x;
    int v = (tid < NB) ? g_bsum[tid] : 0;
    s[tid] = v;
    __syncthreads();
    #pragma unroll
    for (int st = 1; st < 512; st <<= 1) {
        int t = (tid >= st) ? s[tid - st] : 0;
        __syncthreads();
        s[tid] += t;
        __syncthreads();
    }
    if (tid < NB) g_bpre[tid] = s[tid] - v;
    if (tid == 0) g_offs[NN] = NE;
}

__global__ void k_scanC() {
    int i = blockIdx.x * blockDim.x + threadIdx.x;
    if (i < NN) g_offs[i] += g_bpre[i >> 8];
}

// fill CSR buckets: meta = {src, norm}
__global__ void k_fill() {
    int e = blockIdx.x * blockDim.x + threadIdx.x;
    if (e >= NE) return;
    int r = g_rows[e], c = g_cols[e];
    int pos = g_offs[c] + atomicAdd(&g_cur[c], 1);
    float n = g_dinv[r] * g_dinv[c];
    g_meta[pos] = make_int2(r, __float_as_int(n));
}

// layer-1 aggregation: warp per destination node, lane owns feature pair
__global__ void k_gather1(const float* __restrict__ x) {
    int wid  = (blockIdx.x * blockDim.x + threadIdx.x) >> 5;
    int lane = threadIdx.x & 31;
    if (wid >= NN) return;
    int d = wid;
    float dd = g_dinv[d];
    float d2 = dd * dd;
    float2 xs = ((const float2*)x)[d * 32 + lane];     // exact fp32 self term
    float2 acc = make_float2(d2 * xs.x, d2 * xs.y);
    int beg = g_offs[d], end = g_offs[d + 1];
    for (int p = beg; p < end; p++) {
        int2 m = g_meta[p];                            // broadcast load
        float n = __int_as_float(m.y);
        float2 v = __half22float2(g_xh[m.x * 32 + lane]);  // coalesced 128B row
        acc.x = fmaf(n, v.x, acc.x);
        acc.y = fmaf(n, v.y, acc.y);
    }
    ((float2*)g_agg1)[d * 32 + lane] = acc;
}

// h1 = relu(agg1 @ W1 + b1), 64x128 tile, 256 threads
__global__ void k_gemm1(const float* __restrict__ W1, const float* __restrict__ b1) {
    __shared__ float As[64 * 64];
    __shared__ float Bs[64 * 128];
    int tid = threadIdx.x;
    int bnode = blockIdx.x * 64;

    for (int t = tid; t < (64 * 128) / 4; t += 256)
        ((float4*)Bs)[t] = ((const float4*)W1)[t];
    for (int t = tid; t < 64 * 16; t += 256) {
        int lr = t >> 4, q = t & 15;
        int node = bnode + lr;
        float4 v = (node < NN) ? g_agg1[node * 16 + q]
                               : make_float4(0.f, 0.f, 0.f, 0.f);
        ((float4*)As)[t] = v;
    }
    __syncthreads();

    int tx = tid & 31, ty = tid >> 5;
    float acc[8][4];
    #pragma unroll
    for (int i = 0; i < 8; i++)
        #pragma unroll
        for (int j = 0; j < 4; j++) acc[i][j] = 0.0f;

    #pragma unroll 4
    for (int k = 0; k < 64; k++) {
        float4 bb = ((const float4*)Bs)[k * 32 + tx];
        #pragma unroll
        for (int i = 0; i < 8; i++) {
            float a = As[(ty * 8 + i) * 64 + k];
            acc[i][0] = fmaf(a, bb.x, acc[i][0]);
            acc[i][1] = fmaf(a, bb.y, acc[i][1]);
            acc[i][2] = fmaf(a, bb.z, acc[i][2]);
            acc[i][3] = fmaf(a, bb.w, acc[i][3]);
        }
    }

    float4 bias = ((const float4*)b1)[tx];
    #pragma unroll
    for (int i = 0; i < 8; i++) {
        int node = bnode + ty * 8 + i;
        if (node < NN) {
            float4 o;
            o.x = fmaxf(acc[i][0] + bias.x, 0.0f);
            o.y = fmaxf(acc[i][1] + bias.y, 0.0f);
            o.z = fmaxf(acc[i][2] + bias.z, 0.0f);
            o.w = fmaxf(acc[i][3] + bias.w, 0.0f);
            g_h1[(size_t)node * 32 + tx] = o;
        }
    }
}

// t2p = h1 @ W2 (10 real cols, stride 12)
__global__ void k_gemm2(const float* __restrict__ W2) {
    __shared__ float Ws[HIDD * NCLS];
    int tid = threadIdx.x;
    for (int t = tid; t < HIDD * NCLS; t += blockDim.x) Ws[t] = W2[t];
    __syncthreads();
    int node = blockIdx.x * blockDim.x + tid;
    if (node >= NN) return;
    float acc[NCLS];
    #pragma unroll
    for (int c = 0; c < NCLS; c++) acc[c] = 0.0f;
    const float4* row = &g_h1[(size_t)node * 32];
    #pragma unroll 8
    for (int kk = 0; kk < 32; kk++) {
        float4 h = row[kk];
        const float* w = &Ws[kk * 4 * NCLS];
        #pragma unroll
        for (int c = 0; c < NCLS; c++)
            acc[c] += h.x * w[c] + h.y * w[NCLS + c] + h.z * w[2 * NCLS + c] + h.w * w[3 * NCLS + c];
    }
    #pragma unroll
    for (int c = 0; c < NCLS; c++) g_t2p[node * NCP + c] = acc[c];
}

// layer-2 aggregation + bias + self: warp per dest, 3 edge-slots x 10 classes
__global__ void k_gather2(const float* __restrict__ b2) {
    int wid  = (blockIdx.x * blockDim.x + threadIdx.x) >> 5;
    int lane = threadIdx.x & 31;
    if (wid >= NN) return;
    int d = wid;
    int s = lane / 10;          // 0..2 (lanes 30,31 -> s=3, masked below)
    int c = lane - s * 10;
    float acc = 0.0f;
    int beg = g_offs[d], end = g_offs[d + 1];
    if (s < 3) {
        for (int p = beg + s; p < end; p += 3) {
            int2 m = g_meta[p];
            acc = fmaf(__int_as_float(m.y), g_t2p[m.x * NCP + c], acc);
        }
    }
    float a1 = __shfl_sync(0xffffffffu, acc, (lane + 10) & 31);
    float a2 = __shfl_sync(0xffffffffu, acc, (lane + 20) & 31);
    if (lane < 10) {
        float dd = g_dinv[d];
        g_out2p[d * NCP + lane] =
            dd * dd * g_t2p[d * NCP + lane] + b2[lane] + acc + a1 + a2;
    }
}

// per-node log_softmax, block-reduce per class, atomic into g_acc
__global__ void k_final() {
    __shared__ float sred[NCLS * 256];
    int tid = threadIdx.x;
    int node = blockIdx.x * 256 + tid;
    float loc[NCLS];
    #pragma unroll
    for (int c = 0; c < NCLS; c++) loc[c] = 0.0f;
    if (node < NN) {
        const float* rowp = &g_out2p[node * NCP];
        float v[NCLS];
        float m = -1e30f;
        #pragma unroll
        for (int c = 0; c < NCLS; c++) {
            v[c] = rowp[c];
            m = fmaxf(m, v[c]);
        }
        float s = 0.0f;
        #pragma unroll
        for (int c = 0; c < NCLS; c++) s += expf(v[c] - m);
        float lse = m + logf(s);
        #pragma unroll
        for (int c = 0; c < NCLS; c++) loc[c] = v[c] - lse;
    }
    #pragma unroll
    for (int c = 0; c < NCLS; c++) sred[c * 256 + tid] = loc[c];
    __syncthreads();
    for (int st = 128; st > 0; st >>= 1) {
        if (tid < st) {
            #pragma unroll
            for (int c = 0; c < NCLS; c++)
                sred[c * 256 + tid] += sred[c * 256 + tid + st];
        }
        __syncthreads();
    }
    if (tid < NCLS) atomicAdd(&g_acc[tid], sred[tid * 256]);
}

__global__ void k_out(float* __restrict__ out) {
    int c = threadIdx.x;
    if (c < NCLS) out[c] = g_acc[c] * (1.0f / (float)NN);
}

// ---------------- launch ----------------
extern "C" void kernel_launch(void* const* d_in, const int* in_sizes, int n_in,
                              void* d_out, int out_size) {
    const float* x  = (const float*)d_in[0];
    const void*  ei = d_in[1];
    const float* W1 = (const float*)d_in[2];
    const float* b1 = (const float*)d_in[3];
    const float* W2 = (const float*)d_in[4];
    const float* b2 = (const float*)d_in[5];
    float* out = (float*)d_out;

    k_parse       <<<1, 256>>>(ei);
    k_init        <<<(NN + 255) / 256, 256>>>();
    k_edges_degree<<<(NE + 255) / 256, 256>>>(ei);
    k_dinv        <<<(NN + 255) / 256, 256>>>();
    k_xhalf       <<<(NN * 32 + 255) / 256, 256>>>(x);
    k_scanA       <<<NB, 256>>>();
    k_scanB       <<<1, 512>>>();
    k_scanC       <<<(NN + 255) / 256, 256>>>();
    k_fill        <<<(NE + 255) / 256, 256>>>();
    k_gather1     <<<(NN * 32 + 255) / 256, 256>>>(x);
    k_gemm1       <<<(NN + 63) / 64, 256>>>(W1, b1);
    k_gemm2       <<<(NN + 255) / 256, 256>>>(W2);
    k_gather2     <<<(NN * 32 + 255) / 256, 256>>>(b2);
    k_final       <<<(NN + 255) / 256, 256>>>();
    k_out         <<<1, 32>>>(out);
}

// round 7
// speedup vs baseline: 1.9318x; 1.0490x over previous
#include <cuda_runtime.h>
#include <cuda_fp16.h>
#include <math.h>

#define NN   100000
#define NE   1600000
#define INF  64
#define HIDD 128
#define NCLS 10
#define NCP  12
#define NB   ((NN + 255) / 256)     // 391 scan blocks
#define FULL 0xffffffffu

// ---------------- scratch (no allocations allowed) ----------------
__device__ int   g_is64;
__device__ int   g_cnt[NN];
__device__ int   g_cur[NN];
__device__ int   g_offs[NN + 1];
__device__ int   g_bsum[NB];
__device__ int   g_bpre[NB];
__device__ float g_dinv[NN];
__device__ int   g_rows[NE];
__device__ int   g_cols[NE];
__device__ int   g_msrc[NE];          // 6.4 MB : CSR src per slot
__device__ __half2 g_xh[NN * 32];     // 12.8 MB : xs = dinv*x in half
__device__ float4 g_agg1[NN * (INF / 4)];          // 25.6 MB
__device__ float4 g_h1[(size_t)NN * (HIDD / 4)];   // 51.2 MB
__device__ float g_t2s[NN * NCP];                  // 4.8 MB : dinv * (h1 @ W2), stride 12
__device__ float g_out2p[NN * NCP];                // 4.8 MB
__device__ float g_acc[NCLS];

// ---------------- kernels ----------------

// init + dtype sniff (block 0)
__global__ void k_init(const void* __restrict__ ei_raw) {
    __shared__ int s_nz;
    int tid = threadIdx.x;
    int i = blockIdx.x * blockDim.x + tid;
    if (i < NN) { g_cnt[i] = 0; g_cur[i] = 0; }
    if (i < NCLS) g_acc[i] = 0.0f;
    if (tid == 0) s_nz = 0;
    __syncthreads();
    if (blockIdx.x == 0) {
        const unsigned int* w = (const unsigned int*)ei_raw;
        if (w[tid * 2 + 1] != 0u) atomicAdd(&s_nz, 1);
    }
    __syncthreads();
    if (blockIdx.x == 0 && tid == 0) g_is64 = (s_nz == 0) ? 1 : 0;
}

// decode edges (dtype dispatch + clamp) and histogram destinations
__global__ void k_edges_degree(const void* __restrict__ ei_raw) {
    int e = blockIdx.x * blockDim.x + threadIdx.x;
    if (e >= NE) return;
    int r, c;
    if (g_is64) {
        const long long* ei = (const long long*)ei_raw;
        r = (int)ei[e];  c = (int)ei[NE + e];
    } else {
        const int* ei = (const int*)ei_raw;
        r = ei[e];       c = ei[NE + e];
    }
    r = min(max(r, 0), NN - 1);
    c = min(max(c, 0), NN - 1);
    g_rows[e] = r;
    g_cols[e] = c;
    atomicAdd(&g_cnt[c], 1);
}

// scan stage A (+ dinv fused)
__global__ void k_scanA() {
    __shared__ int s[256];
    int tid = threadIdx.x;
    int i = blockIdx.x * 256 + tid;
    int v = (i < NN) ? g_cnt[i] : 0;
    if (i < NN) g_dinv[i] = rsqrtf((float)(v + 1));
    s[tid] = v;
    __syncthreads();
    #pragma unroll
    for (int st = 1; st < 256; st <<= 1) {
        int t = (tid >= st) ? s[tid - st] : 0;
        __syncthreads();
        s[tid] += t;
        __syncthreads();
    }
    if (i < NN) g_offs[i] = s[tid] - v;
    if (tid == 255) g_bsum[blockIdx.x] = s[255];
}

__global__ void k_scanB() {
    __shared__ int s[512];
    int tid = threadIdx.x;
    int v = (tid < NB) ? g_bsum[tid] : 0;
    s[tid] = v;
    __syncthreads();
    #pragma unroll
    for (int st = 1; st < 512; st <<= 1) {
        int t = (tid >= st) ? s[tid - st] : 0;
        __syncthreads();
        s[tid] += t;
        __syncthreads();
    }
    if (tid < NB) g_bpre[tid] = s[tid] - v;
    if (tid == 0) g_offs[NN] = NE;
}

__global__ void k_scanC() {
    int i = blockIdx.x * blockDim.x + threadIdx.x;
    if (i < NN) g_offs[i] += g_bpre[i >> 8];
}

// xs = dinv * x -> half2
__global__ void k_xhalf(const float* __restrict__ x) {
    int i = blockIdx.x * blockDim.x + threadIdx.x;   // NN*32
    if (i < NN * 32) {
        int node = i >> 5;
        float d = g_dinv[node];
        float2 v = ((const float2*)x)[i];
        g_xh[i] = __floats2half2_rn(d * v.x, d * v.y);
    }
}

// fill CSR buckets with src only
__global__ void k_fill() {
    int e = blockIdx.x * blockDim.x + threadIdx.x;
    if (e >= NE) return;
    int c = g_cols[e];
    int pos = g_offs[c] + atomicAdd(&g_cur[c], 1);
    g_msrc[pos] = g_rows[e];
}

// layer-1 aggregation: warp per dest node; meta distributed via shfl chunks.
// agg1[d] = dinv[d] * ( xs[d] + sum_{edges} xs[src] )
__global__ void k_gather1() {
    int wid  = (blockIdx.x * blockDim.x + threadIdx.x) >> 5;
    int lane = threadIdx.x & 31;
    if (wid >= NN) return;
    int d = wid;
    float2 acc = __half22float2(g_xh[d * 32 + lane]);   // self term (xs[d])
    int beg = g_offs[d];
    int deg = g_offs[d + 1] - beg;
    for (int base = 0; base < deg; base += 32) {
        int rem = deg - base;
        int cnt = rem < 32 ? rem : 32;
        int m = (lane < cnt) ? g_msrc[beg + base + lane] : 0;
        for (int j = 0; j < cnt; j++) {
            int src = __shfl_sync(FULL, m, j);
            float2 v = __half22float2(g_xh[src * 32 + lane]);
            acc.x += v.x;
            acc.y += v.y;
        }
    }
    float dd = g_dinv[d];
    acc.x *= dd; acc.y *= dd;
    ((float2*)g_agg1)[d * 32 + lane] = acc;
}

// h1 = relu(agg1 @ W1 + b1), 64x128 tile, 256 threads
__global__ void k_gemm1(const float* __restrict__ W1, const float* __restrict__ b1) {
    __shared__ float As[64 * 64];
    __shared__ float Bs[64 * 128];
    int tid = threadIdx.x;
    int bnode = blockIdx.x * 64;

    for (int t = tid; t < (64 * 128) / 4; t += 256)
        ((float4*)Bs)[t] = ((const float4*)W1)[t];
    for (int t = tid; t < 64 * 16; t += 256) {
        int lr = t >> 4, q = t & 15;
        int node = bnode + lr;
        float4 v = (node < NN) ? g_agg1[node * 16 + q]
                               : make_float4(0.f, 0.f, 0.f, 0.f);
        ((float4*)As)[t] = v;
    }
    __syncthreads();

    int tx = tid & 31, ty = tid >> 5;
    float acc[8][4];
    #pragma unroll
    for (int i = 0; i < 8; i++)
        #pragma unroll
        for (int j = 0; j < 4; j++) acc[i][j] = 0.0f;

    #pragma unroll 4
    for (int k = 0; k < 64; k++) {
        float4 bb = ((const float4*)Bs)[k * 32 + tx];
        #pragma unroll
        for (int i = 0; i < 8; i++) {
            float a = As[(ty * 8 + i) * 64 + k];
            acc[i][0] = fmaf(a, bb.x, acc[i][0]);
            acc[i][1] = fmaf(a, bb.y, acc[i][1]);
            acc[i][2] = fmaf(a, bb.z, acc[i][2]);
            acc[i][3] = fmaf(a, bb.w, acc[i][3]);
        }
    }

    float4 bias = ((const float4*)b1)[tx];
    #pragma unroll
    for (int i = 0; i < 8; i++) {
        int node = bnode + ty * 8 + i;
        if (node < NN) {
            float4 o;
            o.x = fmaxf(acc[i][0] + bias.x, 0.0f);
            o.y = fmaxf(acc[i][1] + bias.y, 0.0f);
            o.z = fmaxf(acc[i][2] + bias.z, 0.0f);
            o.w = fmaxf(acc[i][3] + bias.w, 0.0f);
            g_h1[(size_t)node * 32 + tx] = o;
        }
    }
}

// t2s = dinv * (h1 @ W2), stride-12 rows
__global__ void k_gemm2(const float* __restrict__ W2) {
    __shared__ float Ws[HIDD * NCLS];
    int tid = threadIdx.x;
    for (int t = tid; t < HIDD * NCLS; t += blockDim.x) Ws[t] = W2[t];
    __syncthreads();
    int node = blockIdx.x * blockDim.x + tid;
    if (node >= NN) return;
    float acc[NCLS];
    #pragma unroll
    for (int c = 0; c < NCLS; c++) acc[c] = 0.0f;
    const float4* row = &g_h1[(size_t)node * 32];
    #pragma unroll 8
    for (int kk = 0; kk < 32; kk++) {
        float4 h = row[kk];
        const float* w = &Ws[kk * 4 * NCLS];
        #pragma unroll
        for (int c = 0; c < NCLS; c++)
            acc[c] += h.x * w[c] + h.y * w[NCLS + c] + h.z * w[2 * NCLS + c] + h.w * w[3 * NCLS + c];
    }
    float d = g_dinv[node];
    #pragma unroll
    for (int c = 0; c < NCLS; c++) g_t2s[node * NCP + c] = d * acc[c];
}

// layer-2: out2[d] = dinv[d] * ( t2s[d] + sum_edges t2s[src] ) + b2
// warp per node; 3 groups of 10 lanes; uniform iteration count + shfl distribution
__global__ void k_gather2(const float* __restrict__ b2) {
    int wid  = (blockIdx.x * blockDim.x + threadIdx.x) >> 5;
    int lane = threadIdx.x & 31;
    if (wid >= NN) return;
    int d = wid;
    int s = lane / 10;          // 0..2 active, 3 for lanes 30,31
    int c = lane - s * 10;
    float acc = 0.0f;
    int beg = g_offs[d];
    int deg = g_offs[d + 1] - beg;
    for (int base = 0; base < deg; base += 32) {
        int rem = deg - base;
        int cnt = rem < 32 ? rem : 32;
        int m = (lane < cnt) ? g_msrc[beg + base + lane] : 0;
        int iters = (cnt + 2) / 3;
        for (int jj = 0; jj < iters; jj++) {
            int j = jj * 3 + s;
            int src = __shfl_sync(FULL, m, j < 31 ? j : 31);
            if (s < 3 && j < cnt)
                acc += g_t2s[src * NCP + c];
        }
    }
    float a1 = __shfl_sync(FULL, acc, (lane + 10) & 31);
    float a2 = __shfl_sync(FULL, acc, (lane + 20) & 31);
    if (lane < 10) {
        float dd = g_dinv[d];
        g_out2p[d * NCP + lane] =
            dd * (acc + a1 + a2 + g_t2s[d * NCP + lane]) + b2[lane];
    }
}

// per-node log_softmax, block-reduce per class, atomic into g_acc
__global__ void k_final() {
    __shared__ float sred[NCLS * 256];
    int tid = threadIdx.x;
    int node = blockIdx.x * 256 + tid;
    float loc[NCLS];
    #pragma unroll
    for (int c = 0; c < NCLS; c++) loc[c] = 0.0f;
    if (node < NN) {
        const float* rowp = &g_out2p[node * NCP];
        float v[NCLS];
        float m = -1e30f;
        #pragma unroll
        for (int c = 0; c < NCLS; c++) {
            v[c] = rowp[c];
            m = fmaxf(m, v[c]);
        }
        float s = 0.0f;
        #pragma unroll
        for (int c = 0; c < NCLS; c++) s += expf(v[c] - m);
        float lse = m + logf(s);
        #pragma unroll
        for (int c = 0; c < NCLS; c++) loc[c] = v[c] - lse;
    }
    #pragma unroll
    for (int c = 0; c < NCLS; c++) sred[c * 256 + tid] = loc[c];
    __syncthreads();
    for (int st = 128; st > 0; st >>= 1) {
        if (tid < st) {
            #pragma unroll
            for (int c = 0; c < NCLS; c++)
                sred[c * 256 + tid] += sred[c * 256 + tid + st];
        }
        __syncthreads();
    }
    if (tid < NCLS) atomicAdd(&g_acc[tid], sred[tid * 256]);
}

__global__ void k_out(float* __restrict__ out) {
    int c = threadIdx.x;
    if (c < NCLS) out[c] = g_acc[c] * (1.0f / (float)NN);
}

// ---------------- launch ----------------
extern "C" void kernel_launch(void* const* d_in, const int* in_sizes, int n_in,
                              void* d_out, int out_size) {
    const float* x  = (const float*)d_in[0];
    const void*  ei = d_in[1];
    const float* W1 = (const float*)d_in[2];
    const float* b1 = (const float*)d_in[3];
    const float* W2 = (const float*)d_in[4];
    const float* b2 = (const float*)d_in[5];
    float* out = (float*)d_out;

    k_init        <<<(NN + 255) / 256, 256>>>(ei);
    k_edges_degree<<<(NE + 255) / 256, 256>>>(ei);
    k_scanA       <<<NB, 256>>>();
    k_scanB       <<<1, 512>>>();
    k_scanC       <<<(NN + 255) / 256, 256>>>();
    k_xhalf       <<<(NN * 32 + 255) / 256, 256>>>(x);
    k_fill        <<<(NE + 255) / 256, 256>>>();
    k_gather1     <<<(NN * 32 + 255) / 256, 256>>>();
    k_gemm1       <<<(NN + 63) / 64, 256>>>(W1, b1);
    k_gemm2       <<<(NN + 255) / 256, 256>>>(W2);
    k_gather2     <<<(NN * 32 + 255) / 256, 256>>>(b2);
    k_final       <<<(NN + 255) / 256, 256>>>();
    k_out         <<<1, 32>>>(out);
}